// round 1
// baseline (speedup 1.0000x reference)
#include <cuda_runtime.h>
#include <math.h>

// Problem constants
#define Bsz  4
#define Tseq 2048
#define Cdim 1024
#define Hn   16
#define Dh   64
#define Mrows (Bsz * Tseq)   // 8192

// Scratch (device globals: allocation-free rule)
__device__ float g_qkv[(size_t)3 * Bsz * Hn * Tseq * Dh];  // [3][B*H][T][D]  (~96 MB)
__device__ float g_att[(size_t)Bsz * Tseq * Cdim];         // [B,T,C]        (~32 MB)

// ---------------------------------------------------------------------------
// SGEMM: Y = X @ W^T.  X[M,K] row-major, W[N,K] row-major. 128x128x16 tiles,
// 256 threads, 8x8 interleaved micro-tiles.
// ---------------------------------------------------------------------------

__global__ void __launch_bounds__(256) gemm_qkv_kernel(
    const float* __restrict__ X,    // [8192, 1024]
    const float* __restrict__ W)    // [3072, 1024]
{
    __shared__ float As[128][17];
    __shared__ float Bs[128][17];
    const int K = Cdim;
    const int tid = threadIdx.x;
    const int tx = tid & 15, ty = tid >> 4;
    const int m0 = blockIdx.y * 128;
    const int n0 = blockIdx.x * 128;

    float acc[8][8];
#pragma unroll
    for (int i = 0; i < 8; i++)
#pragma unroll
        for (int j = 0; j < 8; j++) acc[i][j] = 0.f;

    const int lr = tid >> 2;          // 0..63
    const int lk = (tid & 3) << 2;    // 0,4,8,12

    for (int k0 = 0; k0 < K; k0 += 16) {
#pragma unroll
        for (int p = 0; p < 2; p++) {
            int row = lr + p * 64;
            float4 a = *reinterpret_cast<const float4*>(X + (size_t)(m0 + row) * K + k0 + lk);
            As[row][lk + 0] = a.x; As[row][lk + 1] = a.y;
            As[row][lk + 2] = a.z; As[row][lk + 3] = a.w;
            float4 b = *reinterpret_cast<const float4*>(W + (size_t)(n0 + row) * K + k0 + lk);
            Bs[row][lk + 0] = b.x; Bs[row][lk + 1] = b.y;
            Bs[row][lk + 2] = b.z; Bs[row][lk + 3] = b.w;
        }
        __syncthreads();
#pragma unroll
        for (int k = 0; k < 16; k++) {
            float af[8], bf[8];
#pragma unroll
            for (int i = 0; i < 8; i++) af[i] = As[ty + 16 * i][k];
#pragma unroll
            for (int j = 0; j < 8; j++) bf[j] = Bs[tx + 16 * j][k];
#pragma unroll
            for (int i = 0; i < 8; i++)
#pragma unroll
                for (int j = 0; j < 8; j++) acc[i][j] += af[i] * bf[j];
        }
        __syncthreads();
    }

    // Scatter epilogue: n -> (three, h, d); m -> (b, t); write [3][B*H][T][D]
#pragma unroll
    for (int i = 0; i < 8; i++) {
        int m = m0 + ty + 16 * i;
        int b = m >> 11;          // / 2048
        int t = m & 2047;
#pragma unroll
        for (int j = 0; j < 8; j++) {
            int n = n0 + tx + 16 * j;
            int three = n >> 10;
            int rem = n & 1023;
            int h = rem >> 6;
            int d = rem & 63;
            size_t idx = (((size_t)(three * Bsz + b) * Hn + h) * Tseq + t) * Dh + d;
            g_qkv[idx] = acc[i][j];
        }
    }
}

__global__ void __launch_bounds__(256) gemm_proj_kernel(
    const float* __restrict__ W,      // w_proj [1024, 1024]
    const float* __restrict__ bias,   // [1024]
    float* __restrict__ out)          // [8192, 1024]
{
    __shared__ float As[128][17];
    __shared__ float Bs[128][17];
    const int K = Cdim;
    const int tid = threadIdx.x;
    const int tx = tid & 15, ty = tid >> 4;
    const int m0 = blockIdx.y * 128;
    const int n0 = blockIdx.x * 128;
    const float* X = g_att;

    float acc[8][8];
#pragma unroll
    for (int i = 0; i < 8; i++)
#pragma unroll
        for (int j = 0; j < 8; j++) acc[i][j] = 0.f;

    const int lr = tid >> 2;
    const int lk = (tid & 3) << 2;

    for (int k0 = 0; k0 < K; k0 += 16) {
#pragma unroll
        for (int p = 0; p < 2; p++) {
            int row = lr + p * 64;
            float4 a = *reinterpret_cast<const float4*>(X + (size_t)(m0 + row) * K + k0 + lk);
            As[row][lk + 0] = a.x; As[row][lk + 1] = a.y;
            As[row][lk + 2] = a.z; As[row][lk + 3] = a.w;
            float4 b = *reinterpret_cast<const float4*>(W + (size_t)(n0 + row) * K + k0 + lk);
            Bs[row][lk + 0] = b.x; Bs[row][lk + 1] = b.y;
            Bs[row][lk + 2] = b.z; Bs[row][lk + 3] = b.w;
        }
        __syncthreads();
#pragma unroll
        for (int k = 0; k < 16; k++) {
            float af[8], bf[8];
#pragma unroll
            for (int i = 0; i < 8; i++) af[i] = As[ty + 16 * i][k];
#pragma unroll
            for (int j = 0; j < 8; j++) bf[j] = Bs[tx + 16 * j][k];
#pragma unroll
            for (int i = 0; i < 8; i++)
#pragma unroll
                for (int j = 0; j < 8; j++) acc[i][j] += af[i] * bf[j];
        }
        __syncthreads();
    }

#pragma unroll
    for (int i = 0; i < 8; i++) {
        int m = m0 + ty + 16 * i;
#pragma unroll
        for (int j = 0; j < 8; j++) {
            int n = n0 + tx + 16 * j;
            out[(size_t)m * Cdim + n] = acc[i][j] + __ldg(&bias[n]);
        }
    }
}

// ---------------------------------------------------------------------------
// Flash attention (fp32, causal). One block per (bh, 64-row q tile).
// 256 threads, 4x4 interleaved micro-tiles over a 64x64 S tile.
// smem: Qs[64][65], KPs[64][65] (K tile, reused for P), Vs[64][65]  (dynamic)
// ---------------------------------------------------------------------------

__global__ void __launch_bounds__(256) attn_kernel()
{
    extern __shared__ float sm[];
    float* Qs  = sm;               // 64*65
    float* KPs = sm + 64 * 65;     // 64*65
    float* Vs  = sm + 2 * 64 * 65; // 64*65

    const int tid = threadIdx.x;
    const int tx = tid & 15, ty = tid >> 4;
    const int mq = blockIdx.x;       // q tile index, 0..31
    const int bh = blockIdx.y;       // 0..63  (b = bh/16, h = bh%16)
    const int q0 = mq * 64;

    const float* Qg = g_qkv + ((size_t)(0 * 64 + bh) * Tseq + q0) * Dh;
    const float* Kg = g_qkv + (size_t)(1 * 64 + bh) * Tseq * Dh;
    const float* Vg = g_qkv + (size_t)(2 * 64 + bh) * Tseq * Dh;

    const int lrow = tid >> 4;         // 0..15
    const int ld4  = (tid & 15) << 2;  // 0..60

    // Load Q tile [64][64] -> Qs (stride 65)
#pragma unroll
    for (int p = 0; p < 4; p++) {
        int row = lrow + p * 16;
        float4 v = *reinterpret_cast<const float4*>(Qg + (size_t)row * Dh + ld4);
        Qs[row * 65 + ld4 + 0] = v.x; Qs[row * 65 + ld4 + 1] = v.y;
        Qs[row * 65 + ld4 + 2] = v.z; Qs[row * 65 + ld4 + 3] = v.w;
    }

    float m_i[4], l_i[4], o[4][4];
#pragma unroll
    for (int i = 0; i < 4; i++) {
        m_i[i] = -INFINITY; l_i[i] = 0.f;
#pragma unroll
        for (int j = 0; j < 4; j++) o[i][j] = 0.f;
    }

    for (int nt = 0; nt <= mq; nt++) {
        __syncthreads();  // previous P@V reads of KPs/Vs done
        const int kbase = nt * 64;
#pragma unroll
        for (int p = 0; p < 4; p++) {
            int row = lrow + p * 16;
            float4 kv = *reinterpret_cast<const float4*>(Kg + (size_t)(kbase + row) * Dh + ld4);
            KPs[row * 65 + ld4 + 0] = kv.x; KPs[row * 65 + ld4 + 1] = kv.y;
            KPs[row * 65 + ld4 + 2] = kv.z; KPs[row * 65 + ld4 + 3] = kv.w;
            float4 vv = *reinterpret_cast<const float4*>(Vg + (size_t)(kbase + row) * Dh + ld4);
            Vs[row * 65 + ld4 + 0] = vv.x; Vs[row * 65 + ld4 + 1] = vv.y;
            Vs[row * 65 + ld4 + 2] = vv.z; Vs[row * 65 + ld4 + 3] = vv.w;
        }
        __syncthreads();

        // S = Q K^T (4x4 per thread)
        float s[4][4];
#pragma unroll
        for (int i = 0; i < 4; i++)
#pragma unroll
            for (int j = 0; j < 4; j++) s[i][j] = 0.f;
#pragma unroll 8
        for (int kk = 0; kk < 64; kk++) {
            float qa[4], kb[4];
#pragma unroll
            for (int i = 0; i < 4; i++) qa[i] = Qs[(ty + 16 * i) * 65 + kk];
#pragma unroll
            for (int j = 0; j < 4; j++) kb[j] = KPs[(tx + 16 * j) * 65 + kk];
#pragma unroll
            for (int i = 0; i < 4; i++)
#pragma unroll
                for (int j = 0; j < 4; j++) s[i][j] += qa[i] * kb[j];
        }

        // scale + causal mask (diagonal tile only)
#pragma unroll
        for (int i = 0; i < 4; i++)
#pragma unroll
            for (int j = 0; j < 4; j++) {
                s[i][j] *= 0.125f;
                if (nt == mq) {
                    int col = kbase + tx + 16 * j;
                    int row = q0 + ty + 16 * i;
                    if (col > row) s[i][j] = -INFINITY;
                }
            }

        // online softmax update (row groups = 16 lanes sharing ty)
#pragma unroll
        for (int i = 0; i < 4; i++) {
            float mx = s[i][0];
#pragma unroll
            for (int j = 1; j < 4; j++) mx = fmaxf(mx, s[i][j]);
#pragma unroll
            for (int off = 8; off > 0; off >>= 1)
                mx = fmaxf(mx, __shfl_xor_sync(0xffffffffu, mx, off));
            float mnew = fmaxf(m_i[i], mx);
            float alpha = __expf(m_i[i] - mnew);
            float sum = 0.f;
#pragma unroll
            for (int j = 0; j < 4; j++) {
                s[i][j] = __expf(s[i][j] - mnew);
                sum += s[i][j];
            }
#pragma unroll
            for (int off = 8; off > 0; off >>= 1)
                sum += __shfl_xor_sync(0xffffffffu, sum, off);
#pragma unroll
            for (int j = 0; j < 4; j++) o[i][j] *= alpha;
            l_i[i] = l_i[i] * alpha + sum;
            m_i[i] = mnew;
        }

        __syncthreads();  // all threads done reading KPs as K
        // store P transposed: KPs[col][row]
#pragma unroll
        for (int i = 0; i < 4; i++)
#pragma unroll
            for (int j = 0; j < 4; j++)
                KPs[(tx + 16 * j) * 65 + (ty + 16 * i)] = s[i][j];
        __syncthreads();

        // O += P @ V
#pragma unroll 8
        for (int kk = 0; kk < 64; kk++) {
            float pf[4], vf[4];
#pragma unroll
            for (int i = 0; i < 4; i++) pf[i] = KPs[kk * 65 + (ty + 16 * i)];
#pragma unroll
            for (int j = 0; j < 4; j++) vf[j] = Vs[kk * 65 + (tx + 16 * j)];
#pragma unroll
            for (int i = 0; i < 4; i++)
#pragma unroll
                for (int j = 0; j < 4; j++) o[i][j] += pf[i] * vf[j];
        }
    }

    // write [B,T,C] with head offset
    const int b = bh >> 4;
    const int h = bh & 15;
#pragma unroll
    for (int i = 0; i < 4; i++) {
        float inv = 1.f / l_i[i];
        int t = q0 + ty + 16 * i;
#pragma unroll
        for (int j = 0; j < 4; j++) {
            g_att[(size_t)(b * Tseq + t) * Cdim + h * Dh + (tx + 16 * j)] = o[i][j] * inv;
        }
    }
}

// ---------------------------------------------------------------------------

extern "C" void kernel_launch(void* const* d_in, const int* in_sizes, int n_in,
                              void* d_out, int out_size)
{
    const float* x      = (const float*)d_in[0];  // [B,T,C]
    const float* w_qkv  = (const float*)d_in[1];  // [3C, C]
    const float* w_proj = (const float*)d_in[2];  // [C, C]
    const float* b_proj = (const float*)d_in[3];  // [C]
    float* out = (float*)d_out;                   // [B,T,C]

    (void)in_sizes; (void)n_in; (void)out_size;

    // QKV projection: [8192,1024] x [3072,1024]^T -> scatter into g_qkv
    gemm_qkv_kernel<<<dim3(3 * Cdim / 128, Mrows / 128), 256>>>(x, w_qkv);

    // Flash attention
    const int attn_smem = 3 * 64 * 65 * (int)sizeof(float);  // 49920 B
    cudaFuncSetAttribute(attn_kernel, cudaFuncAttributeMaxDynamicSharedMemorySize, attn_smem);
    attn_kernel<<<dim3(Tseq / 64, Bsz * Hn), 256, attn_smem>>>();

    // Output projection + bias
    gemm_proj_kernel<<<dim3(Cdim / 128, Mrows / 128), 256>>>(w_proj, b_proj, out);
}

// round 4
// speedup vs baseline: 1.4850x; 1.4850x over previous
#include <cuda_runtime.h>
#include <cuda_bf16.h>
#include <cstdint>
#include <math.h>

// Problem constants
#define Bsz  4
#define Tseq 2048
#define Cdim 1024
#define Hn   16
#define Dh   64
#define Mrows (Bsz * Tseq)   // 8192
#define Kbig  (3 * Cdim)     // 3072 : split-K layout (X: [hi|hi|lo], W: [hi|lo|hi])

// Scratch (device globals: allocation-free rule)
__device__ float          g_qkv[(size_t)Mrows * 3 * Cdim];      // [8192][3072] fp32 qkv
__device__ __nv_bfloat16  g_xbig[(size_t)Mrows * Kbig];         // [8192][3072]
__device__ __nv_bfloat16  g_wqkvbig[(size_t)3 * Cdim * Kbig];   // [3072][3072]
__device__ __nv_bfloat16  g_attbig[(size_t)Mrows * Kbig];       // [8192][3072]
__device__ __nv_bfloat16  g_wprojbig[(size_t)Cdim * Kbig];      // [1024][3072]

// ---------------------------------------------------------------------------
__device__ __forceinline__ uint32_t smem_u32(const void* p) {
    uint32_t a;
    asm("{ .reg .u64 t; cvta.to.shared.u64 t, %1; cvt.u32.u64 %0, t; }"
        : "=r"(a) : "l"(p));
    return a;
}

__device__ __forceinline__ void cp_async16(uint32_t dst, const void* src) {
    asm volatile("cp.async.cg.shared.global [%0], [%1], 16;" :: "r"(dst), "l"(src));
}
__device__ __forceinline__ void cp_commit() {
    asm volatile("cp.async.commit_group;");
}
template<int N>
__device__ __forceinline__ void cp_wait() {
    asm volatile("cp.async.wait_group %0;" :: "n"(N));
}

__device__ __forceinline__ void ldmatrix_x4(uint32_t* r, uint32_t addr) {
    asm volatile("ldmatrix.sync.aligned.m8n8.x4.shared.b16 {%0,%1,%2,%3}, [%4];"
                 : "=r"(r[0]), "=r"(r[1]), "=r"(r[2]), "=r"(r[3]) : "r"(addr));
}

__device__ __forceinline__ void mma_bf16(float* d, const uint32_t* a, const uint32_t* b) {
    asm volatile(
        "mma.sync.aligned.m16n8k16.row.col.f32.bf16.bf16.f32 "
        "{%0,%1,%2,%3}, {%4,%5,%6,%7}, {%8,%9}, {%0,%1,%2,%3};"
        : "+f"(d[0]), "+f"(d[1]), "+f"(d[2]), "+f"(d[3])
        : "r"(a[0]), "r"(a[1]), "r"(a[2]), "r"(a[3]), "r"(b[0]), "r"(b[1]));
}

// ---------------------------------------------------------------------------
// Activation split: src [rows][1024] fp32 -> dst [rows][3072] bf16  [hi|hi|lo]
// ---------------------------------------------------------------------------
__global__ void __launch_bounds__(256) prep_split_x(
    const float* __restrict__ src, __nv_bfloat16* __restrict__ dst, int rows)
{
    size_t idx = (size_t)blockIdx.x * blockDim.x + threadIdx.x;
    size_t total = (size_t)rows * Cdim;
    if (idx >= total) return;
    size_t r = idx >> 10;
    size_t k = idx & 1023;
    float v = __ldg(src + idx);
    __nv_bfloat16 hi = __float2bfloat16(v);
    __nv_bfloat16 lo = __float2bfloat16(v - __bfloat162float(hi));
    __nv_bfloat16* row = dst + r * Kbig;
    row[k]        = hi;
    row[k + 1024] = hi;
    row[k + 2048] = lo;
}

// ---------------------------------------------------------------------------
// Weight split: src [rows][1024] fp32 -> dst [rows][3072] bf16  [hi|lo|hi]
// Pairs with X so that dot = xhi*whi + xhi*wlo + xlo*whi.
// ---------------------------------------------------------------------------
__global__ void __launch_bounds__(256) prep_split_w(
    const float* __restrict__ src, __nv_bfloat16* __restrict__ dst, int rows)
{
    size_t idx = (size_t)blockIdx.x * blockDim.x + threadIdx.x;
    size_t total = (size_t)rows * Cdim;
    if (idx >= total) return;
    size_t r = idx >> 10;
    size_t k = idx & 1023;
    float v = __ldg(src + idx);
    __nv_bfloat16 hi = __float2bfloat16(v);
    __nv_bfloat16 lo = __float2bfloat16(v - __bfloat162float(hi));
    __nv_bfloat16* row = dst + r * Kbig;
    row[k]        = hi;
    row[k + 1024] = lo;
    row[k + 2048] = hi;
}

// ---------------------------------------------------------------------------
// mma.sync bf16 GEMM: D[M,N] = A[M,Kbig] @ B[N,Kbig]^T  (both K-major bf16)
// CTA 128x128; 8 warps (2x4), warp tile 64x32; K staged 32 at a time,
// 4-stage cp.async pipeline. Smem rows padded to 80B (conflict-free ldmatrix).
// EPI 0: plain fp32 store. EPI 1: +bias.
// ---------------------------------------------------------------------------
#define STAGES 4
#define KSTG   32                      // K elements per stage
#define ROWB   80                      // smem row pitch in bytes (64 data + 16 pad)
#define TILEB  (128 * ROWB)            // 10240 B per operand tile
#define STGB   (2 * TILEB)             // A + B per stage

template<int EPI>
__global__ void __launch_bounds__(256) mm_kernel(
    const __nv_bfloat16* __restrict__ A,
    const __nv_bfloat16* __restrict__ B,
    float* __restrict__ out,
    const float* __restrict__ bias,
    int ldout)
{
    extern __shared__ char sm[];
    const int tid  = threadIdx.x;
    const int wid  = tid >> 5;
    const int lane = tid & 31;
    const int wm   = wid >> 2;        // 0..1  (64 rows each)
    const int wn   = wid & 3;         // 0..3  (32 cols each)

    const int m0 = blockIdx.y * 128;
    const int n0 = blockIdx.x * 128;
    const char* Ag = (const char*)(A + (size_t)m0 * Kbig);
    const char* Bg = (const char*)(B + (size_t)n0 * Kbig);

    const uint32_t sbase = smem_u32(sm);
    const int NCH = Kbig / KSTG;       // 96

    // loader mapping: 512 chunks of 16B per operand tile; 256 threads x 2
    const int lrow0 = tid >> 2;        // chunk row for first half (rows 0..63)
    const int lq    = tid & 3;         // 16B chunk within row

    auto issue_stage = [&](int c, int s) {
        uint32_t dstA = sbase + s * STGB;
        uint32_t dstB = dstA + TILEB;
        const char* srcA = Ag + (size_t)c * (KSTG * 2);
        const char* srcB = Bg + (size_t)c * (KSTG * 2);
#pragma unroll
        for (int h = 0; h < 2; h++) {
            int row = lrow0 + h * 64;
            uint32_t doff = row * ROWB + lq * 16;
            size_t soff = (size_t)row * (Kbig * 2) + lq * 16;
            cp_async16(dstA + doff, srcA + soff);
            cp_async16(dstB + doff, srcB + soff);
        }
    };

    float acc[4][4][4];
#pragma unroll
    for (int i = 0; i < 4; i++)
#pragma unroll
        for (int j = 0; j < 4; j++)
#pragma unroll
            for (int q = 0; q < 4; q++) acc[i][j][q] = 0.f;

    // prologue: fill STAGES-1 stages
#pragma unroll
    for (int s = 0; s < STAGES - 1; s++) { issue_stage(s, s); cp_commit(); }

    // fragment address components
    const int arow = lane & 15;          // A: rows 0..15 of m16 tile
    const int akh  = lane >> 4;          // A: k half (16B)
    const int brow = (lane & 7) + ((lane >> 4) << 3);  // B: n row within n16
    const int bkh  = (lane >> 3) & 1;    // B: k half

    for (int c = 0; c < NCH; c++) {
        cp_wait<STAGES - 2>();
        __syncthreads();
        if (c + STAGES - 1 < NCH) issue_stage(c + STAGES - 1, (c + STAGES - 1) % STAGES);
        cp_commit();

        const int s = c % STAGES;
        const uint32_t Abuf = sbase + s * STGB;
        const uint32_t Bbuf = Abuf + TILEB;

#pragma unroll
        for (int kk = 0; kk < KSTG / 16; kk++) {
            uint32_t afr[4][4];
#pragma unroll
            for (int mi = 0; mi < 4; mi++) {
                uint32_t addr = Abuf + (wm * 64 + mi * 16 + arow) * ROWB + akh * 16 + kk * 32;
                ldmatrix_x4(afr[mi], addr);
            }
            uint32_t bfr[2][4];
#pragma unroll
            for (int nb = 0; nb < 2; nb++) {
                uint32_t addr = Bbuf + (wn * 32 + nb * 16 + brow) * ROWB + bkh * 16 + kk * 32;
                ldmatrix_x4(bfr[nb], addr);
            }
#pragma unroll
            for (int mi = 0; mi < 4; mi++)
#pragma unroll
                for (int ni = 0; ni < 4; ni++)
                    mma_bf16(acc[mi][ni], afr[mi], bfr[ni >> 1] + (ni & 1) * 2);
        }
        __syncthreads();
    }

    // Epilogue: direct float2 stores from fragment layout
    const int r_off = lane >> 2;
    const int c_off = (lane & 3) * 2;
#pragma unroll
    for (int mi = 0; mi < 4; mi++) {
#pragma unroll
        for (int ni = 0; ni < 4; ni++) {
            int col = n0 + wn * 32 + ni * 8 + c_off;
            float bx = 0.f, by = 0.f;
            if (EPI == 1) { bx = __ldg(&bias[col]); by = __ldg(&bias[col + 1]); }
            int row0 = m0 + wm * 64 + mi * 16 + r_off;
            float2 v0 = make_float2(acc[mi][ni][0] + bx, acc[mi][ni][1] + by);
            float2 v1 = make_float2(acc[mi][ni][2] + bx, acc[mi][ni][3] + by);
            *reinterpret_cast<float2*>(out + (size_t)row0 * ldout + col) = v0;
            *reinterpret_cast<float2*>(out + (size_t)(row0 + 8) * ldout + col) = v1;
        }
    }
}

// ---------------------------------------------------------------------------
// Flash attention (fp32, causal). One block per (bh, 64-row q tile).
// Reads g_qkv [8192][3072] fp32 (q|k|v by 1024-col thirds),
// writes g_attbig [8192][3072] bf16 split [hi|hi|lo].
// ---------------------------------------------------------------------------
__global__ void __launch_bounds__(256) attn_kernel()
{
    extern __shared__ float smf[];
    float* Qs  = smf;               // 64*65
    float* KPs = smf + 64 * 65;     // 64*65 (K tile, reused for P^T)
    float* Vs  = smf + 2 * 64 * 65; // 64*65

    const int tid = threadIdx.x;
    const int tx = tid & 15, ty = tid >> 4;
    const int mq = blockIdx.x;
    const int bh = blockIdx.y;
    const int b = bh >> 4;
    const int h = bh & 15;
    const int q0 = mq * 64;

    const float* Qg = g_qkv + ((size_t)(b * Tseq + q0)) * Kbig + h * 64;
    const float* Kg = g_qkv + ((size_t)(b * Tseq)) * Kbig + 1024 + h * 64;
    const float* Vg = g_qkv + ((size_t)(b * Tseq)) * Kbig + 2048 + h * 64;

    const int lrow = tid >> 4;
    const int ld4  = (tid & 15) << 2;

#pragma unroll
    for (int p = 0; p < 4; p++) {
        int row = lrow + p * 16;
        float4 v = *reinterpret_cast<const float4*>(Qg + (size_t)row * Kbig + ld4);
        Qs[row * 65 + ld4 + 0] = v.x; Qs[row * 65 + ld4 + 1] = v.y;
        Qs[row * 65 + ld4 + 2] = v.z; Qs[row * 65 + ld4 + 3] = v.w;
    }

    float m_i[4], l_i[4], o[4][4];
#pragma unroll
    for (int i = 0; i < 4; i++) {
        m_i[i] = -INFINITY; l_i[i] = 0.f;
#pragma unroll
        for (int j = 0; j < 4; j++) o[i][j] = 0.f;
    }

    for (int nt = 0; nt <= mq; nt++) {
        __syncthreads();
        const int kbase = nt * 64;
#pragma unroll
        for (int p = 0; p < 4; p++) {
            int row = lrow + p * 16;
            float4 kv = *reinterpret_cast<const float4*>(Kg + (size_t)(kbase + row) * Kbig + ld4);
            KPs[row * 65 + ld4 + 0] = kv.x; KPs[row * 65 + ld4 + 1] = kv.y;
            KPs[row * 65 + ld4 + 2] = kv.z; KPs[row * 65 + ld4 + 3] = kv.w;
            float4 vv = *reinterpret_cast<const float4*>(Vg + (size_t)(kbase + row) * Kbig + ld4);
            Vs[row * 65 + ld4 + 0] = vv.x; Vs[row * 65 + ld4 + 1] = vv.y;
            Vs[row * 65 + ld4 + 2] = vv.z; Vs[row * 65 + ld4 + 3] = vv.w;
        }
        __syncthreads();

        float s[4][4];
#pragma unroll
        for (int i = 0; i < 4; i++)
#pragma unroll
            for (int j = 0; j < 4; j++) s[i][j] = 0.f;
#pragma unroll 8
        for (int kk = 0; kk < 64; kk++) {
            float qa[4], kb[4];
#pragma unroll
            for (int i = 0; i < 4; i++) qa[i] = Qs[(ty + 16 * i) * 65 + kk];
#pragma unroll
            for (int j = 0; j < 4; j++) kb[j] = KPs[(tx + 16 * j) * 65 + kk];
#pragma unroll
            for (int i = 0; i < 4; i++)
#pragma unroll
                for (int j = 0; j < 4; j++) s[i][j] += qa[i] * kb[j];
        }

#pragma unroll
        for (int i = 0; i < 4; i++)
#pragma unroll
            for (int j = 0; j < 4; j++) {
                s[i][j] *= 0.125f;
                if (nt == mq) {
                    int col = kbase + tx + 16 * j;
                    int row = q0 + ty + 16 * i;
                    if (col > row) s[i][j] = -INFINITY;
                }
            }

#pragma unroll
        for (int i = 0; i < 4; i++) {
            float mx = s[i][0];
#pragma unroll
            for (int j = 1; j < 4; j++) mx = fmaxf(mx, s[i][j]);
#pragma unroll
            for (int off = 8; off > 0; off >>= 1)
                mx = fmaxf(mx, __shfl_xor_sync(0xffffffffu, mx, off));
            float mnew = fmaxf(m_i[i], mx);
            float alpha = __expf(m_i[i] - mnew);
            float sum = 0.f;
#pragma unroll
            for (int j = 0; j < 4; j++) {
                s[i][j] = __expf(s[i][j] - mnew);
                sum += s[i][j];
            }
#pragma unroll
            for (int off = 8; off > 0; off >>= 1)
                sum += __shfl_xor_sync(0xffffffffu, sum, off);
#pragma unroll
            for (int j = 0; j < 4; j++) o[i][j] *= alpha;
            l_i[i] = l_i[i] * alpha + sum;
            m_i[i] = mnew;
        }

        __syncthreads();
#pragma unroll
        for (int i = 0; i < 4; i++)
#pragma unroll
            for (int j = 0; j < 4; j++)
                KPs[(tx + 16 * j) * 65 + (ty + 16 * i)] = s[i][j];
        __syncthreads();

#pragma unroll 8
        for (int kk = 0; kk < 64; kk++) {
            float pf[4], vf[4];
#pragma unroll
            for (int i = 0; i < 4; i++) pf[i] = KPs[kk * 65 + (ty + 16 * i)];
#pragma unroll
            for (int j = 0; j < 4; j++) vf[j] = Vs[kk * 65 + (tx + 16 * j)];
#pragma unroll
            for (int i = 0; i < 4; i++)
#pragma unroll
                for (int j = 0; j < 4; j++) o[i][j] += pf[i] * vf[j];
        }
    }

    // Epilogue: write activation-split bf16 [hi | hi | lo] into g_attbig
#pragma unroll
    for (int i = 0; i < 4; i++) {
        float inv = 1.f / l_i[i];
        int t = q0 + ty + 16 * i;
        size_t mrow = (size_t)(b * Tseq + t) * Kbig + h * 64;
#pragma unroll
        for (int j = 0; j < 4; j++) {
            int cc = tx + 16 * j;
            float val = o[i][j] * inv;
            __nv_bfloat16 hi = __float2bfloat16(val);
            __nv_bfloat16 lo = __float2bfloat16(val - __bfloat162float(hi));
            g_attbig[mrow + cc]        = hi;
            g_attbig[mrow + 1024 + cc] = hi;
            g_attbig[mrow + 2048 + cc] = lo;
        }
    }
}

// ---------------------------------------------------------------------------

extern "C" void kernel_launch(void* const* d_in, const int* in_sizes, int n_in,
                              void* d_out, int out_size)
{
    const float* x      = (const float*)d_in[0];  // [B,T,C]
    const float* w_qkv  = (const float*)d_in[1];  // [3C, C]
    const float* w_proj = (const float*)d_in[2];  // [C, C]
    const float* b_proj = (const float*)d_in[3];  // [C]
    float* out = (float*)d_out;                   // [B,T,C]
    (void)in_sizes; (void)n_in; (void)out_size;

    void *p_xbig, *p_wqkvbig, *p_attbig, *p_wprojbig, *p_qkv;
    cudaGetSymbolAddress(&p_xbig,     g_xbig);
    cudaGetSymbolAddress(&p_wqkvbig,  g_wqkvbig);
    cudaGetSymbolAddress(&p_attbig,   g_attbig);
    cudaGetSymbolAddress(&p_wprojbig, g_wprojbig);
    cudaGetSymbolAddress(&p_qkv,      g_qkv);

    const int mm_smem = STAGES * STGB;  // 4 * 20480 = 81920
    cudaFuncSetAttribute(mm_kernel<0>, cudaFuncAttributeMaxDynamicSharedMemorySize, mm_smem);
    cudaFuncSetAttribute(mm_kernel<1>, cudaFuncAttributeMaxDynamicSharedMemorySize, mm_smem);

    // Split-precision prep: X -> [hi|hi|lo],  W -> [hi|lo|hi]
    prep_split_x<<<(Mrows * Cdim + 255) / 256, 256>>>(x, (__nv_bfloat16*)p_xbig, Mrows);
    prep_split_w<<<(3 * Cdim * Cdim + 255) / 256, 256>>>(w_qkv, (__nv_bfloat16*)p_wqkvbig, 3 * Cdim);
    prep_split_w<<<(Cdim * Cdim + 255) / 256, 256>>>(w_proj, (__nv_bfloat16*)p_wprojbig, Cdim);

    // QKV projection -> g_qkv fp32 [8192][3072]
    mm_kernel<0><<<dim3(3 * Cdim / 128, Mrows / 128), 256, mm_smem>>>(
        (const __nv_bfloat16*)p_xbig, (const __nv_bfloat16*)p_wqkvbig,
        (float*)p_qkv, nullptr, 3 * Cdim);

    // Flash attention (fp32) -> g_attbig bf16 split
    const int attn_smem = 3 * 64 * 65 * (int)sizeof(float);  // 49920
    cudaFuncSetAttribute(attn_kernel, cudaFuncAttributeMaxDynamicSharedMemorySize, attn_smem);
    attn_kernel<<<dim3(Tseq / 64, Bsz * Hn), 256, attn_smem>>>();

    // Output projection + bias
    mm_kernel<1><<<dim3(Cdim / 128, Mrows / 128), 256, mm_smem>>>(
        (const __nv_bfloat16*)p_attbig, (const __nv_bfloat16*)p_wprojbig,
        out, b_proj, Cdim);
}

// round 5
// speedup vs baseline: 2.4459x; 1.6471x over previous
#include <cuda_runtime.h>
#include <cuda_bf16.h>
#include <cuda_fp16.h>
#include <cstdint>
#include <math.h>

// Problem constants
#define Bsz  4
#define Tseq 2048
#define Cdim 1024
#define Hn   16
#define Dh   64
#define Mrows (Bsz * Tseq)   // 8192
#define Kbig  (3 * Cdim)     // 3072 : split-K layout (X: [hi|hi|lo], W: [hi|lo|hi])

// Scratch (device globals: allocation-free rule)
__device__ __nv_bfloat16  g_xbig[(size_t)Mrows * Kbig];         // [8192][3072]
__device__ __nv_bfloat16  g_wqkvbig[(size_t)3 * Cdim * Kbig];   // [3072][3072]
__device__ __nv_bfloat16  g_attbig[(size_t)Mrows * Kbig];       // [8192][3072]
__device__ __nv_bfloat16  g_wprojbig[(size_t)Cdim * Kbig];      // [1024][3072]
__device__ __half         g_q16[(size_t)64 * Tseq * 192];       // [bh][t][qhi|qlo|qhi]
__device__ __half         g_k16[(size_t)64 * Tseq * 192];       // [bh][t][khi|khi|klo]
__device__ __half         g_v16[(size_t)64 * Tseq * 128];       // [bh][t][vhi|vlo]

// ---------------------------------------------------------------------------
__device__ __forceinline__ uint32_t smem_u32(const void* p) {
    uint32_t a;
    asm("{ .reg .u64 t; cvta.to.shared.u64 t, %1; cvt.u32.u64 %0, t; }"
        : "=r"(a) : "l"(p));
    return a;
}
__device__ __forceinline__ void cp_async16(uint32_t dst, const void* src) {
    asm volatile("cp.async.cg.shared.global [%0], [%1], 16;" :: "r"(dst), "l"(src));
}
__device__ __forceinline__ void cp_commit() { asm volatile("cp.async.commit_group;"); }
template<int N>
__device__ __forceinline__ void cp_wait() {
    asm volatile("cp.async.wait_group %0;" :: "n"(N));
}
__device__ __forceinline__ void ldmatrix_x4(uint32_t* r, uint32_t addr) {
    asm volatile("ldmatrix.sync.aligned.m8n8.x4.shared.b16 {%0,%1,%2,%3}, [%4];"
                 : "=r"(r[0]), "=r"(r[1]), "=r"(r[2]), "=r"(r[3]) : "r"(addr));
}
__device__ __forceinline__ void ldmatrix_x4_t(uint32_t* r, uint32_t addr) {
    asm volatile("ldmatrix.sync.aligned.m8n8.x4.trans.shared.b16 {%0,%1,%2,%3}, [%4];"
                 : "=r"(r[0]), "=r"(r[1]), "=r"(r[2]), "=r"(r[3]) : "r"(addr));
}
__device__ __forceinline__ void mma_bf16(float* d, const uint32_t* a, const uint32_t* b) {
    asm volatile(
        "mma.sync.aligned.m16n8k16.row.col.f32.bf16.bf16.f32 "
        "{%0,%1,%2,%3}, {%4,%5,%6,%7}, {%8,%9}, {%0,%1,%2,%3};"
        : "+f"(d[0]), "+f"(d[1]), "+f"(d[2]), "+f"(d[3])
        : "r"(a[0]), "r"(a[1]), "r"(a[2]), "r"(a[3]), "r"(b[0]), "r"(b[1]));
}
__device__ __forceinline__ void mma_f16(float* d, const uint32_t* a, const uint32_t* b) {
    asm volatile(
        "mma.sync.aligned.m16n8k16.row.col.f32.f16.f16.f32 "
        "{%0,%1,%2,%3}, {%4,%5,%6,%7}, {%8,%9}, {%0,%1,%2,%3};"
        : "+f"(d[0]), "+f"(d[1]), "+f"(d[2]), "+f"(d[3])
        : "r"(a[0]), "r"(a[1]), "r"(a[2]), "r"(a[3]), "r"(b[0]), "r"(b[1]));
}

// Fast exp2 on the FMA pipe (x <= 0; clamped; rel err ~2e-6)
__device__ __forceinline__ float exp2p(float x) {
    x = fmaxf(x, -126.0f);
    float r = x + 12582912.0f;                 // 1.5*2^23 round-to-int magic
    float f = x - (r - 12582912.0f);           // f in [-0.5, 0.5]
    int e = ((__float_as_int(r) - 0x4B400000) + 127) << 23;
    float p = 1.3333558146e-3f;
    p = fmaf(p, f, 9.6181291e-3f);
    p = fmaf(p, f, 5.5504109e-2f);
    p = fmaf(p, f, 2.4022651e-1f);
    p = fmaf(p, f, 6.9314718e-1f);
    p = fmaf(p, f, 1.0f);
    return p * __int_as_float(e);
}

// ---------------------------------------------------------------------------
// Split preps for GEMM operands (bf16 3-term)
// ---------------------------------------------------------------------------
__global__ void __launch_bounds__(256) prep_split_x(
    const float* __restrict__ src, __nv_bfloat16* __restrict__ dst, int rows)
{
    size_t idx = (size_t)blockIdx.x * blockDim.x + threadIdx.x;
    size_t total = (size_t)rows * Cdim;
    if (idx >= total) return;
    size_t r = idx >> 10, k = idx & 1023;
    float v = __ldg(src + idx);
    __nv_bfloat16 hi = __float2bfloat16(v);
    __nv_bfloat16 lo = __float2bfloat16(v - __bfloat162float(hi));
    __nv_bfloat16* row = dst + r * Kbig;
    row[k] = hi; row[k + 1024] = hi; row[k + 2048] = lo;
}
__global__ void __launch_bounds__(256) prep_split_w(
    const float* __restrict__ src, __nv_bfloat16* __restrict__ dst, int rows)
{
    size_t idx = (size_t)blockIdx.x * blockDim.x + threadIdx.x;
    size_t total = (size_t)rows * Cdim;
    if (idx >= total) return;
    size_t r = idx >> 10, k = idx & 1023;
    float v = __ldg(src + idx);
    __nv_bfloat16 hi = __float2bfloat16(v);
    __nv_bfloat16 lo = __float2bfloat16(v - __bfloat162float(hi));
    __nv_bfloat16* row = dst + r * Kbig;
    row[k] = hi; row[k + 1024] = lo; row[k + 2048] = hi;
}

// ---------------------------------------------------------------------------
// qkv split-fp16 store (epilogue of the QKV GEMM). m -> (b,t); n -> (sec,h,d).
// ---------------------------------------------------------------------------
__device__ __forceinline__ void store_qkv_pair(int m, int n, float x, float y) {
    int b = m >> 11, t = m & 2047;
    int sec = n >> 10, h = (n >> 6) & 15, d = n & 63;
    int bh = b * Hn + h;
    __half hx = __float2half_rn(x), hy = __float2half_rn(y);
    __half lx = __float2half_rn(x - __half2float(hx));
    __half ly = __float2half_rn(y - __half2float(hy));
    __half2 hi = __halves2half2(hx, hy);
    __half2 lo = __halves2half2(lx, ly);
    if (sec == 0) {
        __half* row = g_q16 + ((size_t)bh * Tseq + t) * 192;
        *(__half2*)(row + d) = hi; *(__half2*)(row + 64 + d) = lo; *(__half2*)(row + 128 + d) = hi;
    } else if (sec == 1) {
        __half* row = g_k16 + ((size_t)bh * Tseq + t) * 192;
        *(__half2*)(row + d) = hi; *(__half2*)(row + 64 + d) = hi; *(__half2*)(row + 128 + d) = lo;
    } else {
        __half* row = g_v16 + ((size_t)bh * Tseq + t) * 128;
        *(__half2*)(row + d) = hi; *(__half2*)(row + 64 + d) = lo;
    }
}

// ---------------------------------------------------------------------------
// mma.sync bf16 GEMM, 128x128 CTA, 8 warps (2x4), warp 64x32, 4-stage cp.async.
// EPI 0: qkv split-fp16 scatter epilogue.  EPI 1: fp32 +bias store.
// ---------------------------------------------------------------------------
#define STAGES 4
#define KSTG   32
#define ROWB   80
#define TILEB  (128 * ROWB)
#define STGB   (2 * TILEB)

template<int EPI>
__global__ void __launch_bounds__(256) mm_kernel(
    const __nv_bfloat16* __restrict__ A,
    const __nv_bfloat16* __restrict__ B,
    float* __restrict__ out,
    const float* __restrict__ bias,
    int ldout)
{
    extern __shared__ char sm[];
    const int tid  = threadIdx.x;
    const int wid  = tid >> 5;
    const int lane = tid & 31;
    const int wm   = wid >> 2;
    const int wn   = wid & 3;

    const int m0 = blockIdx.y * 128;
    const int n0 = blockIdx.x * 128;
    const char* Ag = (const char*)(A + (size_t)m0 * Kbig);
    const char* Bg = (const char*)(B + (size_t)n0 * Kbig);

    const uint32_t sbase = smem_u32(sm);
    const int NCH = Kbig / KSTG;

    const int lrow0 = tid >> 2;
    const int lq    = tid & 3;

    auto issue_stage = [&](int c, int s) {
        uint32_t dstA = sbase + s * STGB;
        uint32_t dstB = dstA + TILEB;
        const char* srcA = Ag + (size_t)c * (KSTG * 2);
        const char* srcB = Bg + (size_t)c * (KSTG * 2);
#pragma unroll
        for (int h = 0; h < 2; h++) {
            int row = lrow0 + h * 64;
            uint32_t doff = row * ROWB + lq * 16;
            size_t soff = (size_t)row * (Kbig * 2) + lq * 16;
            cp_async16(dstA + doff, srcA + soff);
            cp_async16(dstB + doff, srcB + soff);
        }
    };

    float acc[4][4][4];
#pragma unroll
    for (int i = 0; i < 4; i++)
#pragma unroll
        for (int j = 0; j < 4; j++)
#pragma unroll
            for (int q = 0; q < 4; q++) acc[i][j][q] = 0.f;

#pragma unroll
    for (int s = 0; s < STAGES - 1; s++) { issue_stage(s, s); cp_commit(); }

    const int arow = lane & 15;
    const int akh  = lane >> 4;
    const int brow = (lane & 7) + ((lane >> 4) << 3);
    const int bkh  = (lane >> 3) & 1;

    for (int c = 0; c < NCH; c++) {
        cp_wait<STAGES - 2>();
        __syncthreads();
        if (c + STAGES - 1 < NCH) issue_stage(c + STAGES - 1, (c + STAGES - 1) % STAGES);
        cp_commit();

        const int s = c % STAGES;
        const uint32_t Abuf = sbase + s * STGB;
        const uint32_t Bbuf = Abuf + TILEB;

#pragma unroll
        for (int kk = 0; kk < KSTG / 16; kk++) {
            uint32_t afr[4][4];
#pragma unroll
            for (int mi = 0; mi < 4; mi++) {
                uint32_t addr = Abuf + (wm * 64 + mi * 16 + arow) * ROWB + akh * 16 + kk * 32;
                ldmatrix_x4(afr[mi], addr);
            }
            uint32_t bfr[2][4];
#pragma unroll
            for (int nb = 0; nb < 2; nb++) {
                uint32_t addr = Bbuf + (wn * 32 + nb * 16 + brow) * ROWB + bkh * 16 + kk * 32;
                ldmatrix_x4(bfr[nb], addr);
            }
#pragma unroll
            for (int mi = 0; mi < 4; mi++)
#pragma unroll
                for (int ni = 0; ni < 4; ni++)
                    mma_bf16(acc[mi][ni], afr[mi], bfr[ni >> 1] + (ni & 1) * 2);
        }
        __syncthreads();
    }

    const int r_off = lane >> 2;
    const int c_off = (lane & 3) * 2;
#pragma unroll
    for (int mi = 0; mi < 4; mi++) {
#pragma unroll
        for (int ni = 0; ni < 4; ni++) {
            int col = n0 + wn * 32 + ni * 8 + c_off;
            int row0 = m0 + wm * 64 + mi * 16 + r_off;
            if (EPI == 0) {
                store_qkv_pair(row0,     col, acc[mi][ni][0], acc[mi][ni][1]);
                store_qkv_pair(row0 + 8, col, acc[mi][ni][2], acc[mi][ni][3]);
            } else {
                float bx = __ldg(&bias[col]), by = __ldg(&bias[col + 1]);
                float2 v0 = make_float2(acc[mi][ni][0] + bx, acc[mi][ni][1] + by);
                float2 v1 = make_float2(acc[mi][ni][2] + bx, acc[mi][ni][3] + by);
                *reinterpret_cast<float2*>(out + (size_t)row0 * ldout + col) = v0;
                *reinterpret_cast<float2*>(out + (size_t)(row0 + 8) * ldout + col) = v1;
            }
        }
    }
}

// ---------------------------------------------------------------------------
// Tensor-core flash attention. Block = (128 q rows, bh). 8 warps, warp m16.
// K-tile = 64. Q frags register-resident (fp16 split K=192). V fp16 split.
// Writes g_attbig bf16 [hi|hi|lo].
// ---------------------------------------------------------------------------
#define KROWB 400    // 64 t-rows x (192 halves = 384B + 16 pad)
#define VROWB 272    // 64 t-rows x (128 halves = 256B + 16 pad)
#define ATT_SMEM (64 * KROWB + 64 * VROWB)   // 43008

__global__ void __launch_bounds__(256) attn_kernel()
{
    extern __shared__ char smc[];
    const uint32_t Kbuf = smem_u32(smc);
    const uint32_t Vbuf = Kbuf + 64 * KROWB;

    const int tid  = threadIdx.x;
    const int wid  = tid >> 5;
    const int lane = tid & 31;
    const int r    = lane >> 2;
    const int c2   = (lane & 3) * 2;
    const int mq = 15 - blockIdx.x;          // heavy tiles first
    const int bh = blockIdx.y;
    const int q0 = mq * 128;

    // B-operand lane mapping (plain, for K)
    const int brow = (lane & 7) + ((lane >> 4) << 3);
    const int bkh  = (lane >> 3) & 1;
    // B-operand lane mapping (trans, for V)
    const int trow = (lane & 7) + ((lane >> 3) & 1) * 8;
    const int tcol = ((lane >> 4) & 1) * 8;

    // Load Q fragments (register resident), rows q0+wid*16 .. +15, K=192
    const __half* qbase = g_q16 + (size_t)bh * Tseq * 192;
    uint32_t qa[12][4];
#pragma unroll
    for (int kk = 0; kk < 12; kk++) {
#pragma unroll
        for (int e = 0; e < 4; e++) {
            int row = q0 + wid * 16 + r + (e & 1) * 8;
            int col = kk * 16 + c2 + (e >> 1) * 8;
            qa[kk][e] = *reinterpret_cast<const uint32_t*>(qbase + (size_t)row * 192 + col);
        }
    }

    float m2[2] = {-INFINITY, -INFINITY};
    float l[2]  = {0.f, 0.f};
    float oacc[8][4];
#pragma unroll
    for (int f = 0; f < 8; f++)
#pragma unroll
        for (int e = 0; e < 4; e++) oacc[f][e] = 0.f;

    const char* kg = (const char*)(g_k16 + (size_t)bh * Tseq * 192);
    const char* vg = (const char*)(g_v16 + (size_t)bh * Tseq * 128);
    const int rr = tid >> 2;
    const int cq = tid & 3;
    const int nts = 2 * mq + 2;
    const float Csc = 0.125f * 1.4426950408889634f;

    for (int nt = 0; nt < nts; nt++) {
        __syncthreads();
        const int kb = nt * 64;
        // Load K (64x384B) and V (64x256B) tiles
#pragma unroll
        for (int q = 0; q < 6; q++) {
            int ch = cq * 6 + q;
            cp_async16(Kbuf + rr * KROWB + ch * 16, kg + (size_t)(kb + rr) * 384 + ch * 16);
        }
#pragma unroll
        for (int q = 0; q < 4; q++) {
            int ch = cq * 4 + q;
            cp_async16(Vbuf + rr * VROWB + ch * 16, vg + (size_t)(kb + rr) * 256 + ch * 16);
        }
        cp_commit();
        cp_wait<0>();
        __syncthreads();

        // S = Q'K'^T  (K=192, n=64)
        float sacc[8][4];
#pragma unroll
        for (int f = 0; f < 8; f++)
#pragma unroll
            for (int e = 0; e < 4; e++) sacc[f][e] = 0.f;
#pragma unroll
        for (int kk = 0; kk < 12; kk++) {
#pragma unroll
            for (int nb = 0; nb < 4; nb++) {
                uint32_t bf[4];
                ldmatrix_x4(bf, Kbuf + (nb * 16 + brow) * KROWB + bkh * 16 + kk * 32);
                mma_f16(sacc[nb * 2],     qa[kk], bf);
                mma_f16(sacc[nb * 2 + 1], qa[kk], bf + 2);
            }
        }

        // scale + causal mask (in base-2 domain)
        const bool diag = (nt >= 2 * mq);
#pragma unroll
        for (int f = 0; f < 8; f++)
#pragma unroll
            for (int e = 0; e < 4; e++) {
                float y = sacc[f][e] * Csc;
                if (diag) {
                    int col_g = kb + f * 8 + c2 + (e & 1);
                    int row_g = q0 + wid * 16 + r + (e >> 1) * 8;
                    if (col_g > row_g) y = -1e30f;
                }
                sacc[f][e] = y;
            }

        // online softmax per row-half; pack P as fp16 A-fragments
        uint32_t ph[8][2];
#pragma unroll
        for (int hh = 0; hh < 2; hh++) {
            float mx = -1e30f;
#pragma unroll
            for (int f = 0; f < 8; f++) {
                mx = fmaxf(mx, sacc[f][hh * 2]);
                mx = fmaxf(mx, sacc[f][hh * 2 + 1]);
            }
            mx = fmaxf(mx, __shfl_xor_sync(0xffffffffu, mx, 1));
            mx = fmaxf(mx, __shfl_xor_sync(0xffffffffu, mx, 2));
            float mnew = fmaxf(m2[hh], mx);
            float alpha = exp2p(m2[hh] - mnew);
            float sum = 0.f;
#pragma unroll
            for (int f = 0; f < 8; f++) {
                float p0 = exp2p(sacc[f][hh * 2] - mnew);
                float p1 = exp2p(sacc[f][hh * 2 + 1] - mnew);
                sum += p0 + p1;
                __half2 pp = __floats2half2_rn(p0, p1);
                ph[f][hh] = *reinterpret_cast<uint32_t*>(&pp);
            }
            sum += __shfl_xor_sync(0xffffffffu, sum, 1);
            sum += __shfl_xor_sync(0xffffffffu, sum, 2);
            l[hh] = l[hh] * alpha + sum;
            m2[hh] = mnew;
#pragma unroll
            for (int f = 0; f < 8; f++) {
                oacc[f][hh * 2]     *= alpha;
                oacc[f][hh * 2 + 1] *= alpha;
            }
        }

        // O += P @ [Vhi] + P @ [Vlo]   (ldmatrix.trans on [t][d] tiles)
#pragma unroll
        for (int kk2 = 0; kk2 < 4; kk2++) {
            uint32_t pa[4] = { ph[2 * kk2][0], ph[2 * kk2][1],
                               ph[2 * kk2 + 1][0], ph[2 * kk2 + 1][1] };
#pragma unroll
            for (int nb = 0; nb < 4; nb++) {
                uint32_t addr = Vbuf + (kk2 * 16 + trow) * VROWB + (nb * 16 + tcol) * 2;
                uint32_t bhi[4], blo[4];
                ldmatrix_x4_t(bhi, addr);
                mma_f16(oacc[nb * 2],     pa, bhi);
                mma_f16(oacc[nb * 2 + 1], pa, bhi + 2);
                ldmatrix_x4_t(blo, addr + 128);
                mma_f16(oacc[nb * 2],     pa, blo);
                mma_f16(oacc[nb * 2 + 1], pa, blo + 2);
            }
        }
    }

    // Epilogue: O/l -> bf16 split [hi|hi|lo] into g_attbig
    const int b = bh >> 4, h = bh & 15;
#pragma unroll
    for (int hh = 0; hh < 2; hh++) {
        float inv = 1.f / l[hh];
        int t = q0 + wid * 16 + r + hh * 8;
        __nv_bfloat16* mrow = g_attbig + ((size_t)(b * Tseq + t)) * Kbig + h * 64;
#pragma unroll
        for (int f = 0; f < 8; f++) {
            int d = f * 8 + c2;
            float x = oacc[f][hh * 2] * inv;
            float y = oacc[f][hh * 2 + 1] * inv;
            __nv_bfloat16 hx = __float2bfloat16(x), hy = __float2bfloat16(y);
            __nv_bfloat16 lx = __float2bfloat16(x - __bfloat162float(hx));
            __nv_bfloat16 ly = __float2bfloat16(y - __bfloat162float(hy));
            __nv_bfloat162 hi; hi.x = hx; hi.y = hy;
            __nv_bfloat162 lo; lo.x = lx; lo.y = ly;
            *reinterpret_cast<__nv_bfloat162*>(mrow + d) = hi;
            *reinterpret_cast<__nv_bfloat162*>(mrow + 1024 + d) = hi;
            *reinterpret_cast<__nv_bfloat162*>(mrow + 2048 + d) = lo;
        }
    }
}

// ---------------------------------------------------------------------------

extern "C" void kernel_launch(void* const* d_in, const int* in_sizes, int n_in,
                              void* d_out, int out_size)
{
    const float* x      = (const float*)d_in[0];
    const float* w_qkv  = (const float*)d_in[1];
    const float* w_proj = (const float*)d_in[2];
    const float* b_proj = (const float*)d_in[3];
    float* out = (float*)d_out;
    (void)in_sizes; (void)n_in; (void)out_size;

    void *p_xbig, *p_wqkvbig, *p_attbig, *p_wprojbig;
    cudaGetSymbolAddress(&p_xbig,     g_xbig);
    cudaGetSymbolAddress(&p_wqkvbig,  g_wqkvbig);
    cudaGetSymbolAddress(&p_attbig,   g_attbig);
    cudaGetSymbolAddress(&p_wprojbig, g_wprojbig);

    const int mm_smem = STAGES * STGB;  // 81920
    cudaFuncSetAttribute(mm_kernel<0>, cudaFuncAttributeMaxDynamicSharedMemorySize, mm_smem);
    cudaFuncSetAttribute(mm_kernel<1>, cudaFuncAttributeMaxDynamicSharedMemorySize, mm_smem);
    cudaFuncSetAttribute(attn_kernel, cudaFuncAttributeMaxDynamicSharedMemorySize, ATT_SMEM);

    // Split-precision prep: X -> [hi|hi|lo],  W -> [hi|lo|hi]
    prep_split_x<<<(Mrows * Cdim + 255) / 256, 256>>>(x, (__nv_bfloat16*)p_xbig, Mrows);
    prep_split_w<<<(3 * Cdim * Cdim + 255) / 256, 256>>>(w_qkv, (__nv_bfloat16*)p_wqkvbig, 3 * Cdim);
    prep_split_w<<<(Cdim * Cdim + 255) / 256, 256>>>(w_proj, (__nv_bfloat16*)p_wprojbig, Cdim);

    // QKV projection -> split-fp16 q16/k16/v16 (fused epilogue)
    mm_kernel<0><<<dim3(3 * Cdim / 128, Mrows / 128), 256, mm_smem>>>(
        (const __nv_bfloat16*)p_xbig, (const __nv_bfloat16*)p_wqkvbig,
        nullptr, nullptr, 0);

    // Tensor-core flash attention -> g_attbig bf16 split
    attn_kernel<<<dim3(16, 64), 256, ATT_SMEM>>>();

    // Output projection + bias
    mm_kernel<1><<<dim3(Cdim / 128, Mrows / 128), 256, mm_smem>>>(
        (const __nv_bfloat16*)p_attbig, (const __nv_bfloat16*)p_wprojbig,
        out, b_proj, Cdim);
}